// round 4
// baseline (speedup 1.0000x reference)
#include <cuda_runtime.h>
#include <cstdint>

// Elman RNN, unit-split layout for occupancy.
// N=2048, T=512, I=32, H=64, O=1.
// 1024 blocks x 64 threads (2 warps). Thread j owns hidden unit j for BOTH of
// the block's 2 samples. Weights: 48 f32x2 pairs (96 regs) per thread.
// Operand [h(64)|x(32)] per sample double-buffered in smem; one __syncthreads
// per step. <=146 regs -> 7 blocks/SM -> single wave, ~3.5 warps/SMSP.

#define TT 512

typedef unsigned long long ull;

__device__ __forceinline__ float tanh_acc(float s) {
    float e = __expf(2.0f * s);
    return 1.0f - __fdividef(2.0f, e + 1.0f);
}

__global__ void __launch_bounds__(64, 7) rnn_unit_kernel(
    const float* __restrict__ x,      // [N, T, I]
    const float* __restrict__ W_ih,   // [H, I]
    const float* __restrict__ W_hh,   // [H, H]
    const float* __restrict__ b_ih,   // [H]
    const float* __restrict__ b_hh,   // [H]
    const float* __restrict__ fc_w,   // [1, H]
    const float* __restrict__ fc_b,   // [1]
    float* __restrict__ out)          // [N, 1]
{
    __shared__ __align__(16) float buf[2][2][96];  // [parity][sample][ h(64)|x(32) ]
    __shared__ float wsum[2][2];                   // [warp][sample] head partials

    const int j  = threadIdx.x;        // hidden unit 0..63
    const int n0 = 2 * blockIdx.x;

    // ---- per-thread weights: k=0..63 -> W_hh row j, k=64..95 -> W_ih row j ----
    ull W[48];
    {
        const ull* p = reinterpret_cast<const ull*>(W_hh + j * 64);
        #pragma unroll
        for (int k = 0; k < 32; k++) W[k] = __ldg(p + k);
        const ull* q = reinterpret_cast<const ull*>(W_ih + j * 32);
        #pragma unroll
        for (int k = 0; k < 16; k++) W[32 + k] = __ldg(q + k);
    }
    const float bias = b_ih[j] + b_hh[j];

    // x staging role: warp s (= j>>5) stages x column c (= j&31) of sample s
    const int s_ld = j >> 5;
    const int c_ld = j & 31;
    const float* xl = x + (size_t)(n0 + s_ld) * TT * 32 + c_ld;

    // ---- init: h0 = ones, stage x_0 ----
    buf[0][0][j] = 1.0f;
    buf[0][1][j] = 1.0f;
    buf[0][s_ld][64 + c_ld] = __ldg(xl);
    __syncthreads();

    float h0 = 1.0f, h1 = 1.0f;       // this unit's h for samples 0,1

    for (int t = 0; t < TT; t++) {
        const int cur = t & 1;
        const int nxt = cur ^ 1;

        // prefetch next x (coalesced; hidden under the FMA loop)
        const int tn = (t + 1 < TT) ? (t + 1) : (TT - 1);
        const float xn = __ldg(xl + tn * 32);

        const ulonglong2* vp0 = reinterpret_cast<const ulonglong2*>(&buf[cur][0][0]);
        const ulonglong2* vp1 = reinterpret_cast<const ulonglong2*>(&buf[cur][1][0]);

        // two f32x2 chains per sample (RAW spacing >= 4 cy)
        float2 sd = make_float2(bias, 0.0f);
        ull a0 = *reinterpret_cast<ull*>(&sd);  // sample0 chain A (bias-seeded)
        ull b0 = 0ull;                          // sample0 chain B
        ull a1 = a0;                            // sample1 chain A
        ull b1 = 0ull;                          // sample1 chain B

        #pragma unroll
        for (int g = 0; g < 24; g++) {
            const ulonglong2 v0 = vp0[g];
            const ulonglong2 v1 = vp1[g];
            asm("fma.rn.f32x2 %0, %1, %2, %0;" : "+l"(a0) : "l"(v0.x), "l"(W[2 * g]));
            asm("fma.rn.f32x2 %0, %1, %2, %0;" : "+l"(a1) : "l"(v1.x), "l"(W[2 * g]));
            asm("fma.rn.f32x2 %0, %1, %2, %0;" : "+l"(b0) : "l"(v0.y), "l"(W[2 * g + 1]));
            asm("fma.rn.f32x2 %0, %1, %2, %0;" : "+l"(b1) : "l"(v1.y), "l"(W[2 * g + 1]));
        }

        asm("add.rn.f32x2 %0, %0, %1;" : "+l"(a0) : "l"(b0));
        asm("add.rn.f32x2 %0, %0, %1;" : "+l"(a1) : "l"(b1));
        float r0x, r0y, r1x, r1y;
        asm("mov.b64 {%0, %1}, %2;" : "=f"(r0x), "=f"(r0y) : "l"(a0));
        asm("mov.b64 {%0, %1}, %2;" : "=f"(r1x), "=f"(r1y) : "l"(a1));

        h0 = tanh_acc(r0x + r0y);
        h1 = tanh_acc(r1x + r1y);

        buf[nxt][0][j] = h0;
        buf[nxt][1][j] = h1;
        buf[nxt][s_ld][64 + c_ld] = xn;
        __syncthreads();
    }

    // ---- output head: sigmoid(h . fc_w + fc_b) per sample ----
    const float w = fc_w[j];
    float p0 = h0 * w;
    float p1 = h1 * w;
    #pragma unroll
    for (int o = 16; o; o >>= 1) {
        p0 += __shfl_xor_sync(0xffffffffu, p0, o);
        p1 += __shfl_xor_sync(0xffffffffu, p1, o);
    }
    if ((j & 31) == 0) {
        wsum[j >> 5][0] = p0;
        wsum[j >> 5][1] = p1;
    }
    __syncthreads();
    if (j < 2) {
        const float s = wsum[0][j] + wsum[1][j] + fc_b[0];
        out[n0 + j] = __fdividef(1.0f, 1.0f + __expf(-s));
    }
}

extern "C" void kernel_launch(void* const* d_in, const int* in_sizes, int n_in,
                              void* d_out, int out_size) {
    const float* x    = (const float*)d_in[0];
    const float* W_ih = (const float*)d_in[1];
    const float* W_hh = (const float*)d_in[2];
    const float* b_ih = (const float*)d_in[3];
    const float* b_hh = (const float*)d_in[4];
    const float* fc_w = (const float*)d_in[5];
    const float* fc_b = (const float*)d_in[6];
    float* out = (float*)d_out;

    rnn_unit_kernel<<<1024, 64>>>(x, W_ih, W_hh, b_ih, b_hh, fc_w, fc_b, out);
}